// round 1
// baseline (speedup 1.0000x reference)
#include <cuda_runtime.h>
#include <cuda_bf16.h>

// AdaptiveTokenSelector:
//   out[0 .. B*S*512)        = top-512 values per score row, sorted descending (f32)
//   out[B*S*512 .. +B*S)     = k_per_query = int(256 + 256*sigmoid(Q.W + b)) as f32
//
// topk strategy per row (one CTA, 512 threads, 8 keys/thread in registers):
//   1. float -> order-preserving uint key
//   2. 4x 8-bit MSD radix-select passes (shared 256-bin histogram + warp suffix-scan)
//      -> exact threshold key T, count kGT of keys strictly > T
//   3. warp-aggregated-atomic compaction of keys > T into shared[0..kGT),
//      fill [kGT..512) with T
//   4. bitonic sort 512 keys descending in shared
//   5. key -> float, store

#define TPB      512
#define ROWLEN   4096
#define KSEL     512

__device__ __forceinline__ unsigned f2k(float f) {
    unsigned u = __float_as_uint(f);
    // negative: flip all bits; positive: flip sign bit -> monotonic unsigned
    return u ^ ((unsigned)((int)u >> 31) | 0x80000000u);
}

__device__ __forceinline__ float k2f(unsigned k) {
    unsigned u = (k & 0x80000000u) ? (k ^ 0x80000000u) : ~k;
    return __uint_as_float(u);
}

__global__ __launch_bounds__(TPB) void topk_kernel(const float* __restrict__ scores,
                                                   float* __restrict__ out) {
    __shared__ unsigned bins[256];
    __shared__ unsigned skeys[KSEL];
    __shared__ unsigned sh_prefix, sh_kr, sh_cnt;

    const int t = threadIdx.x;
    const long long row = blockIdx.x;
    const float4* src = (const float4*)(scores + row * (long long)ROWLEN);

    // ---- load 8 floats/thread, convert to sortable keys (registers) ----
    unsigned keys[8];
    {
        float4 a = src[t];
        float4 b = src[t + TPB];
        keys[0] = f2k(a.x); keys[1] = f2k(a.y); keys[2] = f2k(a.z); keys[3] = f2k(a.w);
        keys[4] = f2k(b.x); keys[5] = f2k(b.y); keys[6] = f2k(b.z); keys[7] = f2k(b.w);
    }

    if (t == 0) { sh_prefix = 0; sh_kr = KSEL; }

    // ---- 4-pass MSD radix select of the 512th-largest key ----
    unsigned mask = 0;
    #pragma unroll
    for (int pass = 0; pass < 4; pass++) {
        const int shift = 24 - 8 * pass;
        if (t < 256) bins[t] = 0;
        __syncthreads();

        const unsigned prefix = sh_prefix;
        const unsigned kr     = sh_kr;
        #pragma unroll
        for (int i = 0; i < 8; i++)
            if ((keys[i] & mask) == prefix)
                atomicAdd(&bins[(keys[i] >> shift) & 0xFF], 1u);
        __syncthreads();

        if (t < 32) {
            // lane t owns bins [8t, 8t+8); suffix-scan across lanes via shfl
            unsigned c[8], partial = 0;
            #pragma unroll
            for (int i = 0; i < 8; i++) { c[i] = bins[t * 8 + i]; partial += c[i]; }
            unsigned s = partial;
            #pragma unroll
            for (int off = 1; off < 32; off <<= 1) {
                unsigned v = __shfl_down_sync(0xFFFFFFFFu, s, off);
                if (t + off < 32) s += v;
            }
            unsigned cum = s - partial;  // count of matching keys in all higher bins
            #pragma unroll
            for (int i = 7; i >= 0; i--) {
                unsigned nc = cum + c[i];
                if (cum < kr && nc >= kr) {        // crossing bin: unique globally
                    sh_prefix = prefix | ((unsigned)(t * 8 + i) << shift);
                    sh_kr = kr - cum;              // still needed within this bin
                }
                cum = nc;
            }
        }
        mask |= 0xFFu << shift;
        __syncthreads();
    }

    const unsigned T   = sh_prefix;       // exact 512th-largest key value
    const unsigned kGT = KSEL - sh_kr;    // # keys strictly greater than T

    if (t == 0) sh_cnt = 0;
    __syncthreads();

    // ---- compact keys > T via warp-aggregated atomics ----
    const unsigned lane = t & 31;
    const unsigned lt_mask = (lane == 0) ? 0u : (0xFFFFFFFFu >> (32 - lane));
    #pragma unroll
    for (int i = 0; i < 8; i++) {
        bool p = keys[i] > T;
        unsigned bal = __ballot_sync(0xFFFFFFFFu, p);
        unsigned base = 0;
        if (lane == 0 && bal) base = atomicAdd(&sh_cnt, (unsigned)__popc(bal));
        base = __shfl_sync(0xFFFFFFFFu, base, 0);
        if (p) skeys[base + __popc(bal & lt_mask)] = keys[i];
    }
    __syncthreads();
    if ((unsigned)t >= kGT) skeys[t] = T;   // fill ties
    __syncthreads();

    // ---- bitonic sort 512 keys, descending ----
    #pragma unroll 1
    for (int k = 2; k <= KSEL; k <<= 1) {
        #pragma unroll 1
        for (int j = k >> 1; j > 0; j >>= 1) {
            int ixj = t ^ j;
            if (ixj > t) {
                unsigned a = skeys[t], b = skeys[ixj];
                bool desc = ((t & k) == 0);
                if (desc ? (a < b) : (a > b)) { skeys[t] = b; skeys[ixj] = a; }
            }
            __syncthreads();
        }
    }

    out[row * (long long)KSEL + t] = k2f(skeys[t]);
}

// k_per_query: one CTA (256 threads) per (b,s) row of Q
__global__ __launch_bounds__(256) void imp_kernel(const float* __restrict__ Q,
                                                  const float* __restrict__ W,
                                                  const float* __restrict__ bias,
                                                  float* __restrict__ outk,
                                                  int D) {
    __shared__ float red[8];
    const long long row = blockIdx.x;
    const float4* q4 = (const float4*)(Q + row * (long long)D);
    const float4* w4 = (const float4*)W;

    float sum = 0.0f;
    for (int i = threadIdx.x; i < (D >> 2); i += blockDim.x) {
        float4 q = q4[i], w = w4[i];
        sum += q.x * w.x + q.y * w.y + q.z * w.z + q.w * w.w;
    }
    #pragma unroll
    for (int off = 16; off; off >>= 1) sum += __shfl_down_sync(0xFFFFFFFFu, sum, off);
    if ((threadIdx.x & 31) == 0) red[threadIdx.x >> 5] = sum;
    __syncthreads();
    if (threadIdx.x == 0) {
        float s = bias[0];
        #pragma unroll
        for (int w = 0; w < 8; w++) s += red[w];
        float imp = 1.0f / (1.0f + expf(-s));
        int k = (int)(256.0f + 256.0f * imp);   // trunc toward zero, matches .astype(int32)
        outk[row] = (float)k;
    }
}

extern "C" void kernel_launch(void* const* d_in, const int* in_sizes, int n_in,
                              void* d_out, int out_size) {
    const float* Q      = (const float*)d_in[0];
    const float* scores = (const float*)d_in[1];
    const float* W      = (const float*)d_in[2];
    const float* b      = (const float*)d_in[3];

    const int D = in_sizes[2];                        // 1024
    const long long BS = (long long)in_sizes[0] / D;  // B*S = 16384

    float* out = (float*)d_out;

    topk_kernel<<<(unsigned)BS, TPB>>>(scores, out);

    if ((long long)out_size >= BS * KSEL + BS)
        imp_kernel<<<(unsigned)BS, 256>>>(Q, W, b, out + BS * KSEL, D);
}

// round 2
// speedup vs baseline: 1.0476x; 1.0476x over previous
#include <cuda_runtime.h>
#include <cuda_bf16.h>

// AdaptiveTokenSelector:
//   out[0 .. B*S*512)        = top-512 values per score row, sorted descending (f32)
//   out[B*S*512 .. +B*S)     = k_per_query = int(256 + 256*sigmoid(Q.W + b)) as f32
//
// One CTA (512 threads) per row:
//   - 8 keys/thread register-resident, float -> order-preserving uint
//   - 4x 8-bit MSD radix select with warp-aggregated (__match_any_sync) histograms
//   - ballot-aggregated compaction of survivors (> threshold), pad with threshold
//   - hybrid bitonic sort of 512 keys: smem stages only for j>=32, shfl for j<32
//   - fused importance gate: k = int(256 + 256*sigmoid(Q_row . W + b))

#define TPB      512
#define ROWLEN   4096
#define KSEL     512

__device__ __forceinline__ unsigned f2k(float f) {
    unsigned u = __float_as_uint(f);
    return u ^ ((unsigned)((int)u >> 31) | 0x80000000u);
}

__device__ __forceinline__ float k2f(unsigned k) {
    unsigned u = (k & 0x80000000u) ? (k ^ 0x80000000u) : ~k;
    return __uint_as_float(u);
}

__global__ __launch_bounds__(TPB) void topk_kernel(const float* __restrict__ scores,
                                                   const float* __restrict__ Q,
                                                   const float* __restrict__ W,
                                                   const float* __restrict__ bias,
                                                   float* __restrict__ out,
                                                   float* __restrict__ outk,
                                                   int D) {
    __shared__ unsigned bins[256];
    __shared__ unsigned skeys[KSEL];
    __shared__ float red[TPB / 32];
    __shared__ unsigned sh_prefix, sh_kr, sh_cnt;

    const int t = threadIdx.x;
    const unsigned lane = t & 31;
    const int wid = t >> 5;
    const long long row = blockIdx.x;
    const float4* src = (const float4*)(scores + row * (long long)ROWLEN);

    // ---- load 8 floats/thread, convert to sortable keys (registers) ----
    unsigned keys[8];
    {
        float4 a = src[t];
        float4 b = src[t + TPB];
        keys[0] = f2k(a.x); keys[1] = f2k(a.y); keys[2] = f2k(a.z); keys[3] = f2k(a.w);
        keys[4] = f2k(b.x); keys[5] = f2k(b.y); keys[6] = f2k(b.z); keys[7] = f2k(b.w);
    }

    // ---- fused importance gate: partial dot of Q_row . W ----
    if (outk) {
        const float2* q2 = (const float2*)(Q + row * (long long)D);
        const float2* w2 = (const float2*)W;
        float s = 0.0f;
        for (int i = t; i < (D >> 1); i += TPB) {
            float2 q = q2[i], w = w2[i];
            s += q.x * w.x + q.y * w.y;
        }
        #pragma unroll
        for (int off = 16; off; off >>= 1) s += __shfl_down_sync(0xFFFFFFFFu, s, off);
        if (lane == 0) red[wid] = s;
    }

    if (t == 0) { sh_prefix = 0; sh_kr = KSEL; sh_cnt = 0; }

    // ---- 4-pass MSD radix select of the 512th-largest key ----
    unsigned mask = 0;
    #pragma unroll
    for (int pass = 0; pass < 4; pass++) {
        const int shift = 24 - 8 * pass;
        if (t < 256) bins[t] = 0;
        __syncthreads();

        if (pass == 0 && outk && t == 0) {
            float s = bias[0];
            #pragma unroll
            for (int w = 0; w < TPB / 32; w++) s += red[w];
            float imp = 1.0f / (1.0f + expf(-s));
            outk[row] = (float)(int)(256.0f + 256.0f * imp);
        }

        const unsigned prefix = sh_prefix;
        const unsigned kr     = sh_kr;
        // warp-aggregated histogram: one atomic per distinct bin per warp
        #pragma unroll
        for (int i = 0; i < 8; i++) {
            unsigned bin = 0xFFFFFFFFu;
            if ((keys[i] & mask) == prefix) bin = (keys[i] >> shift) & 0xFF;
            unsigned grp = __match_any_sync(0xFFFFFFFFu, bin);
            if (bin != 0xFFFFFFFFu && lane == (unsigned)(__ffs(grp) - 1))
                atomicAdd(&bins[bin], (unsigned)__popc(grp));
        }
        __syncthreads();

        if (t < 32) {
            // lane t owns bins [8t, 8t+8); suffix-scan across lanes via shfl
            unsigned c[8], partial = 0;
            #pragma unroll
            for (int i = 0; i < 8; i++) { c[i] = bins[t * 8 + i]; partial += c[i]; }
            unsigned s = partial;
            #pragma unroll
            for (int off = 1; off < 32; off <<= 1) {
                unsigned v = __shfl_down_sync(0xFFFFFFFFu, s, off);
                if (t + off < 32) s += v;
            }
            unsigned cum = s - partial;  // matching keys in all higher bins
            #pragma unroll
            for (int i = 7; i >= 0; i--) {
                unsigned nc = cum + c[i];
                if (cum < kr && nc >= kr) {        // crossing bin: unique globally
                    sh_prefix = prefix | ((unsigned)(t * 8 + i) << shift);
                    sh_kr = kr - cum;
                }
                cum = nc;
            }
        }
        mask |= 0xFFu << shift;
        __syncthreads();
    }

    const unsigned T   = sh_prefix;       // exact 512th-largest key
    const unsigned kGT = KSEL - sh_kr;    // # keys strictly greater than T

    // ---- compact keys > T via ballot-aggregated atomics ----
    const unsigned lt_mask = (lane == 0) ? 0u : (0xFFFFFFFFu >> (32 - lane));
    #pragma unroll
    for (int i = 0; i < 8; i++) {
        bool p = keys[i] > T;
        unsigned bal = __ballot_sync(0xFFFFFFFFu, p);
        unsigned base = 0;
        if (lane == 0 && bal) base = atomicAdd(&sh_cnt, (unsigned)__popc(bal));
        base = __shfl_sync(0xFFFFFFFFu, base, 0);
        if (p) skeys[base + __popc(bal & lt_mask)] = keys[i];
    }
    __syncthreads();
    if ((unsigned)t >= kGT) skeys[t] = T;   // pad ties
    __syncthreads();

    // ---- hybrid bitonic sort (descending), element t in register v ----
    unsigned v = skeys[t];

    // k = 2..32: j < 32 -> pure shfl, no barriers
    #pragma unroll
    for (int k2 = 2; k2 <= 32; k2 <<= 1) {
        #pragma unroll
        for (int j = k2 >> 1; j > 0; j >>= 1) {
            unsigned o = __shfl_xor_sync(0xFFFFFFFFu, v, j);
            bool up    = ((t & k2) == 0);
            bool lower = ((t & j)  == 0);
            v = (up == lower) ? max(v, o) : min(v, o);
        }
    }
    // k = 64..512: j >= 32 via smem (2 bars each), j < 32 via shfl
    #pragma unroll
    for (int k2 = 64; k2 <= KSEL; k2 <<= 1) {
        for (int j = k2 >> 1; j >= 32; j >>= 1) {
            skeys[t] = v;
            __syncthreads();
            unsigned o = skeys[t ^ j];
            __syncthreads();
            bool up    = ((t & k2) == 0);
            bool lower = ((t & j)  == 0);
            v = (up == lower) ? max(v, o) : min(v, o);
        }
        #pragma unroll
        for (int j = 16; j > 0; j >>= 1) {
            unsigned o = __shfl_xor_sync(0xFFFFFFFFu, v, j);
            bool up    = ((t & k2) == 0);
            bool lower = ((t & j)  == 0);
            v = (up == lower) ? max(v, o) : min(v, o);
        }
    }

    out[row * (long long)KSEL + t] = k2f(v);
}

extern "C" void kernel_launch(void* const* d_in, const int* in_sizes, int n_in,
                              void* d_out, int out_size) {
    const float* Q      = (const float*)d_in[0];
    const float* scores = (const float*)d_in[1];
    const float* W      = (const float*)d_in[2];
    const float* b      = (const float*)d_in[3];

    const int D = in_sizes[2];                        // 1024
    const long long BS = (long long)in_sizes[0] / D;  // B*S = 16384

    float* out  = (float*)d_out;
    float* outk = ((long long)out_size >= BS * KSEL + BS) ? out + BS * KSEL : nullptr;

    topk_kernel<<<(unsigned)BS, TPB>>>(scores, Q, W, b, out, outk, D);
}